// round 14
// baseline (speedup 1.0000x reference)
#include <cuda_runtime.h>
#include <cuda_fp16.h>
#include <cstdint>

#define DIM 256
#define NQ  8192
#define NE  8192
#define NW  64               // 64 int32 words per row (256 int8)
#define ZQ_ELEMS (NQ * DIM)
#define NTILE 32             // code tiles of 256
#define NBLK  128
#define NTHR  512
#define LIST_CAP 4096

// smem: As 16K | Bs 2x64K | gmin16 fp16 64x512 = 64K  -> 212992 B
#define AS_OFF   0
#define BS_OFF   16384
#define GM_OFF   (16384 + 131072)
#define SMEM_SC  (16384 + 131072 + 65536)

// ---------------- device scratch (device-side references only) ----------------
__device__ float g_znorm[NQ * DIM];
__device__ float g_znorm2[NQ];
__device__ float g_zinv[NQ];
__device__ float g_zdel[NQ];
__device__ int   g_qz[NQ * NW];
__device__ float g_enorm[NE * DIM];
__device__ float g_enorm2[NE];
__device__ float g_einv[NE];
__device__ int   g_qeT[NW * NE];     // word-major: [word][code]
__device__ unsigned g_demaxU;
__device__ float g_partial[NQ];
__device__ unsigned g_count;
__device__ unsigned g_gen;

// ---------------- async-copy helpers (sm_80-era PTX) ----------------
__device__ __forceinline__ uint32_t smem_u32(const void* p) {
    uint32_t a;
    asm("{ .reg .u64 t; cvta.to.shared.u64 t, %1; cvt.u32.u64 %0, t; }" : "=r"(a) : "l"(p));
    return a;
}
__device__ __forceinline__ void cp16(uint32_t dst, const void* src) {
    asm volatile("cp.async.cg.shared.global [%0], [%1], 16;" :: "r"(dst), "l"(src));
}
__device__ __forceinline__ void cp_commit() { asm volatile("cp.async.commit_group;"); }
template <int N>
__device__ __forceinline__ void cp_wait() { asm volatile("cp.async.wait_group %0;" :: "n"(N)); }

// ---------------- grid barrier (128 blocks co-resident: 1 block/SM) ----------
__device__ __forceinline__ void gridbar(unsigned expect) {
    __threadfence();
    __syncthreads();
    if (threadIdx.x == 0) {
        unsigned t = atomicAdd(&g_count, 1);
        if (t == NBLK - 1) {
            g_count = 0;
            __threadfence();
            atomicAdd(&g_gen, 1);
        } else {
            while (atomicAdd(&g_gen, 0) < expect) { }
            __threadfence();
        }
    }
    __syncthreads();
}

// ---------------- the whole pipeline in ONE kernel ----------------
__global__ __launch_bounds__(NTHR, 1)
void vq_fused(const float* __restrict__ z_in, const float* __restrict__ e_in,
              float* __restrict__ zq_out, float* __restrict__ idxf_out,
              float* __restrict__ loss_out, int write_zq) {
    extern __shared__ char smem[];
    int*    As     = (int*)(smem + AS_OFF);     // [64 words][64 rows]
    int*    Bs     = (int*)(smem + BS_OFF);     // [2][64 words][256 codes]
    __half* gmin16 = (__half*)(smem + GM_OFF);  // [64 rows][512 groups-of-16]
    __shared__ float s_thr[64];
    __shared__ unsigned long long s_best[64];
    __shared__ int s_cnt;
    __shared__ unsigned s_gen0;

    const int tid = threadIdx.x;
    const int tx  = tid & 31;
    const int wid = tid >> 5;

    if (tid == 0) s_gen0 = g_gen;
    __syncthreads();
    const unsigned gen0 = s_gen0;

    // ================= Phase 1: L2-normalize + int8 quantize (16384 rows) ======
    {
        int warpG = blockIdx.x * 16 + wid;            // 0..2047
        #pragma unroll 1
        for (int it = 0; it < 8; it++) {
            int r16 = warpG + it * 2048;              // 0..16383
            int is_code = (r16 < NE);
            int row = is_code ? r16 : (r16 - NE);
            const float* in = is_code ? e_in : z_in;
            float* outv = is_code ? g_enorm : g_znorm;

            const float4* src = (const float4*)(in + (size_t)row * DIM);
            float4 v0 = src[tx];
            float4 v1 = src[tx + 32];
            float s = v0.x*v0.x + v0.y*v0.y + v0.z*v0.z + v0.w*v0.w
                    + v1.x*v1.x + v1.y*v1.y + v1.z*v1.z + v1.w*v1.w;
            #pragma unroll
            for (int off = 16; off; off >>= 1) s += __shfl_xor_sync(0xffffffffu, s, off);
            float inv = 1.0f / fmaxf(sqrtf(s), 1e-12f);
            v0.x *= inv; v0.y *= inv; v0.z *= inv; v0.w *= inv;
            v1.x *= inv; v1.y *= inv; v1.z *= inv; v1.w *= inv;
            float4* dst = (float4*)(outv + (size_t)row * DIM);
            dst[tx]      = v0;
            dst[tx + 32] = v1;

            float vals[8] = {v0.x, v0.y, v0.z, v0.w, v1.x, v1.y, v1.z, v1.w};
            float s2 = 0.f;
            #pragma unroll
            for (int j = 0; j < 8; j++) s2 += vals[j] * vals[j];
            #pragma unroll
            for (int off = 16; off; off >>= 1) s2 += __shfl_xor_sync(0xffffffffu, s2, off);

            float mx = 0.f;
            #pragma unroll
            for (int j = 0; j < 8; j++) mx = fmaxf(mx, fabsf(vals[j]));
            #pragma unroll
            for (int off = 16; off; off >>= 1) mx = fmaxf(mx, __shfl_xor_sync(0xffffffffu, mx, off));
            float sc    = 127.0f / mx;
            float scinv = mx / 127.0f;

            int h[8];
            float dsum = 0.f;
            #pragma unroll
            for (int j = 0; j < 8; j++) {
                h[j] = (int)rintf(vals[j] * sc);
                float e = vals[j] - (float)h[j] * scinv;
                dsum += e * e;
            }
            #pragma unroll
            for (int off = 16; off; off >>= 1) dsum += __shfl_xor_sync(0xffffffffu, dsum, off);

            int w0 = (h[0] & 0xFF) | ((h[1] & 0xFF) << 8) | ((h[2] & 0xFF) << 16) | (h[3] << 24);
            int w1 = (h[4] & 0xFF) | ((h[5] & 0xFF) << 8) | ((h[6] & 0xFF) << 16) | (h[7] << 24);
            if (is_code) {
                // word-major for transpose-free cp.async in phase 2
                g_qeT[(size_t)tx * NE + row]        = w0;
                g_qeT[(size_t)(tx + 32) * NE + row] = w1;
            } else {
                g_qz[(size_t)row * NW + tx]      = w0;
                g_qz[(size_t)row * NW + 32 + tx] = w1;
            }
            if (tx == 0) {
                float del = sqrtf(dsum);
                if (is_code) {
                    g_enorm2[row] = s2; g_einv[row] = scinv;
                    atomicMax(&g_demaxU, __float_as_uint(del));
                } else {
                    g_znorm2[row] = s2; g_zinv[row] = scinv; g_zdel[row] = del;
                }
            }
        }
    }
    gridbar(gen0 + 1);

    // ================= Phase 2: dp4a screen (8 rows x 4 codes per thread) ======
    const int wm = wid >> 1;          // 0..7 -> rows wm*8..+7
    const int cg = wid & 1;           // codes cg*128 + tx*4 .. +3
    const int qbase = blockIdx.x * 64;

    // A load, transposed into smem [word][row]
    {
        int row = tid >> 3, p = tid & 7;     // 64 rows x 8 threads
        #pragma unroll
        for (int j = 0; j < 2; j++) {
            int w = p * 8 + j * 4;
            int4 v = *(const int4*)&g_qz[(size_t)(qbase + row) * NW + w];
            As[(w + 0) * 64 + row] = v.x;
            As[(w + 1) * 64 + row] = v.y;
            As[(w + 2) * 64 + row] = v.z;
            As[(w + 3) * 64 + row] = v.w;
        }
    }

    const uint32_t bs_base = smem_u32(Bs);

    // issue tile 0 (4096 16B units / 512 thr = 8 each); src is word-major: coalesced
    {
        #pragma unroll
        for (int j = 0; j < 8; j++) {
            int u  = tid + j * 512;          // 0..4095
            int w  = u >> 6;                  // word
            int c4 = u & 63;                  // 16B unit within 256 codes
            cp16(bs_base + (uint32_t)u * 16,
                 &g_qeT[(size_t)w * NE + 0 * 256 + c4 * 4]);
        }
        cp_commit();
    }

    int acc[8][4];

    #pragma unroll 1
    for (int t = 0; t < NTILE; t++) {
        if (t + 1 < NTILE) {
            uint32_t bdst = bs_base + (uint32_t)(((t + 1) & 1) * 65536);
            #pragma unroll
            for (int j = 0; j < 8; j++) {
                int u  = tid + j * 512;
                int w  = u >> 6;
                int c4 = u & 63;
                cp16(bdst + (uint32_t)u * 16,
                     &g_qeT[(size_t)w * NE + (t + 1) * 256 + c4 * 4]);
            }
            cp_commit();
            cp_wait<1>();
        } else {
            cp_wait<0>();
        }
        __syncthreads();

        #pragma unroll
        for (int i = 0; i < 8; i++) {
            acc[i][0] = 0; acc[i][1] = 0; acc[i][2] = 0; acc[i][3] = 0;
        }
        const int* B = Bs + (t & 1) * 16384 + cg * 128;
        #pragma unroll 8
        for (int kw = 0; kw < 64; kw++) {
            int4 a0 = *(const int4*)&As[kw * 64 + wm * 8];
            int4 a1 = *(const int4*)&As[kw * 64 + wm * 8 + 4];
            int4 b  = *(const int4*)&B[kw * 256 + tx * 4];
            acc[0][0] = __dp4a(a0.x, b.x, acc[0][0]); acc[0][1] = __dp4a(a0.x, b.y, acc[0][1]);
            acc[0][2] = __dp4a(a0.x, b.z, acc[0][2]); acc[0][3] = __dp4a(a0.x, b.w, acc[0][3]);
            acc[1][0] = __dp4a(a0.y, b.x, acc[1][0]); acc[1][1] = __dp4a(a0.y, b.y, acc[1][1]);
            acc[1][2] = __dp4a(a0.y, b.z, acc[1][2]); acc[1][3] = __dp4a(a0.y, b.w, acc[1][3]);
            acc[2][0] = __dp4a(a0.z, b.x, acc[2][0]); acc[2][1] = __dp4a(a0.z, b.y, acc[2][1]);
            acc[2][2] = __dp4a(a0.z, b.z, acc[2][2]); acc[2][3] = __dp4a(a0.z, b.w, acc[2][3]);
            acc[3][0] = __dp4a(a0.w, b.x, acc[3][0]); acc[3][1] = __dp4a(a0.w, b.y, acc[3][1]);
            acc[3][2] = __dp4a(a0.w, b.z, acc[3][2]); acc[3][3] = __dp4a(a0.w, b.w, acc[3][3]);
            acc[4][0] = __dp4a(a1.x, b.x, acc[4][0]); acc[4][1] = __dp4a(a1.x, b.y, acc[4][1]);
            acc[4][2] = __dp4a(a1.x, b.z, acc[4][2]); acc[4][3] = __dp4a(a1.x, b.w, acc[4][3]);
            acc[5][0] = __dp4a(a1.y, b.x, acc[5][0]); acc[5][1] = __dp4a(a1.y, b.y, acc[5][1]);
            acc[5][2] = __dp4a(a1.y, b.z, acc[5][2]); acc[5][3] = __dp4a(a1.y, b.w, acc[5][3]);
            acc[6][0] = __dp4a(a1.z, b.x, acc[6][0]); acc[6][1] = __dp4a(a1.z, b.y, acc[6][1]);
            acc[6][2] = __dp4a(a1.z, b.z, acc[6][2]); acc[6][3] = __dp4a(a1.z, b.w, acc[6][3]);
            acc[7][0] = __dp4a(a1.w, b.x, acc[7][0]); acc[7][1] = __dp4a(a1.w, b.y, acc[7][1]);
            acc[7][2] = __dp4a(a1.w, b.z, acc[7][2]); acc[7][3] = __dp4a(a1.w, b.w, acc[7][3]);
        }

        // epilogue: per-row per-16-code fp16 min
        {
            int colb = t * 256 + cg * 128 + tx * 4;
            float4 e2  = *(const float4*)&g_enorm2[colb];
            float4 civ = *(const float4*)&g_einv[colb];
            float4 z2a = *(const float4*)&g_znorm2[qbase + wm * 8];
            float4 z2b = *(const float4*)&g_znorm2[qbase + wm * 8 + 4];
            float4 qia = *(const float4*)&g_zinv[qbase + wm * 8];
            float4 qib = *(const float4*)&g_zinv[qbase + wm * 8 + 4];
            float z2arr[8] = {z2a.x, z2a.y, z2a.z, z2a.w, z2b.x, z2b.y, z2b.z, z2b.w};
            float qiarr[8] = {qia.x, qia.y, qia.z, qia.w, qib.x, qib.y, qib.z, qib.w};
            int g16 = t * 16 + cg * 8 + (tx >> 2);
            #pragma unroll
            for (int i = 0; i < 8; i++) {
                float sc = qiarr[i];
                float k0 = z2arr[i] + e2.x - 2.0f * ((float)acc[i][0] * (sc * civ.x));
                float k1 = z2arr[i] + e2.y - 2.0f * ((float)acc[i][1] * (sc * civ.y));
                float k2 = z2arr[i] + e2.z - 2.0f * ((float)acc[i][2] * (sc * civ.z));
                float k3 = z2arr[i] + e2.w - 2.0f * ((float)acc[i][3] * (sc * civ.w));
                float m = fminf(fminf(k0, k1), fminf(k2, k3));
                m = fminf(m, __shfl_xor_sync(0xffffffffu, m, 1));
                m = fminf(m, __shfl_xor_sync(0xffffffffu, m, 2));
                if ((tx & 3) == 0)
                    gmin16[(wm * 8 + i) * 512 + g16] = __float2half_rn(m);
            }
        }
        __syncthreads();
    }

    // init tail shared state
    if (tid == 0) s_cnt = 0;
    if (tid < 64) s_best[tid] = 0xFFFFFFFFFFFFFFFFull;
    __syncthreads();

    // ---- stage A: per-row lm + threshold (4 rows per warp) ----
    {
        float D = __uint_as_float(g_demaxU);
        #pragma unroll
        for (int k = 0; k < 4; k++) {
            int r = wid * 4 + k;
            float lm = 3.4e38f;
            const __half* gr = &gmin16[r * 512];
            #pragma unroll
            for (int p = 0; p < 2; p++) {
                uint4 v = *(const uint4*)&gr[p * 256 + tx * 8];
                uint32_t ws[4] = {v.x, v.y, v.z, v.w};
                #pragma unroll
                for (int u = 0; u < 4; u++) {
                    float2 f = __half22float2(*(__half2*)&ws[u]);
                    lm = fminf(lm, fminf(f.x, f.y));
                }
            }
            #pragma unroll
            for (int off = 16; off; off >>= 1) lm = fminf(lm, __shfl_xor_sync(0xffffffffu, lm, off));
            if (tx == 0) {
                float dq = g_zdel[qbase + r];
                float M = 2.0f * (dq + D + dq * D);
                s_thr[r] = lm + 2.0f * M + 4e-3f;    // sound window + fp16 slack
            }
        }
    }
    __syncthreads();

    // ---- stage B: scan + push candidate (row, group16) into list ----
    int* list = As;   // reuse As region: 4096 ints
    {
        #pragma unroll 1
        for (int i = 0; i < 8; i++) {
            int u4 = tid + i * 512;                  // uint4 index over 64x512 halves
            int r = u4 >> 6;
            float thr = s_thr[r];
            uint4 v = *(const uint4*)&gmin16[u4 * 8];
            int gbase = (u4 & 63) * 8;
            uint32_t ws[4] = {v.x, v.y, v.z, v.w};
            #pragma unroll
            for (int u = 0; u < 4; u++) {
                float2 f = __half22float2(*(__half2*)&ws[u]);
                if (f.x <= thr) { int p = atomicAdd(&s_cnt, 1); if (p < LIST_CAP) list[p] = (r << 16) | (gbase + u * 2); }
                if (f.y <= thr) { int p = atomicAdd(&s_cnt, 1); if (p < LIST_CAP) list[p] = (r << 16) | (gbase + u * 2 + 1); }
            }
        }
    }
    __syncthreads();
    int ncand = s_cnt;

    // ---- stage C: exact rescore (warp per entry; 16 codes per entry) ----
    if (ncand <= LIST_CAP) {
        #pragma unroll 1
        for (int e = wid; e < ncand; e += 16) {
            int ent = list[e];
            int r   = ent >> 16;
            int g16 = ent & 0xFFFF;
            int rowg = qbase + r;
            float z2r = g_znorm2[rowg];
            const float4* zvw = (const float4*)&g_znorm[(size_t)rowg * DIM];
            float4 za = zvw[tx], zb = zvw[tx + 32];
            #pragma unroll 1
            for (int kk = 0; kk < 16; kk++) {
                int code = g16 * 16 + kk;
                const float4* ev = (const float4*)&g_enorm[(size_t)code * DIM];
                float4 ea = ev[tx], eb = ev[tx + 32];
                float d = za.x*ea.x + za.y*ea.y + za.z*ea.z + za.w*ea.w
                        + zb.x*eb.x + zb.y*eb.y + zb.z*eb.z + zb.w*eb.w;
                #pragma unroll
                for (int off = 16; off; off >>= 1) d += __shfl_xor_sync(0xffffffffu, d, off);
                if (tx == 0) {
                    float key = z2r + g_enorm2[code] - 2.0f * d;
                    unsigned long long p =
                        ((unsigned long long)__float_as_uint(key) << 32) | (unsigned)code;
                    atomicMin(&s_best[r], p);
                }
            }
        }
    } else {
        // sound fallback (practically never)
        #pragma unroll 1
        for (int e = wid; e < 64 * 512; e += 16) {
            int r   = e >> 9;
            int g16 = e & 511;
            if (__half2float(gmin16[r * 512 + g16]) > s_thr[r]) continue;
            int rowg = qbase + r;
            float z2r = g_znorm2[rowg];
            const float4* zvw = (const float4*)&g_znorm[(size_t)rowg * DIM];
            float4 za = zvw[tx], zb = zvw[tx + 32];
            for (int kk = 0; kk < 16; kk++) {
                int code = g16 * 16 + kk;
                const float4* ev = (const float4*)&g_enorm[(size_t)code * DIM];
                float4 ea = ev[tx], eb = ev[tx + 32];
                float d = za.x*ea.x + za.y*ea.y + za.z*ea.z + za.w*ea.w
                        + zb.x*eb.x + zb.y*eb.y + zb.z*eb.z + zb.w*eb.w;
                #pragma unroll
                for (int off = 16; off; off >>= 1) d += __shfl_xor_sync(0xffffffffu, d, off);
                if (tx == 0) {
                    float key = z2r + g_enorm2[code] - 2.0f * d;
                    unsigned long long p =
                        ((unsigned long long)__float_as_uint(key) << 32) | (unsigned)code;
                    atomicMin(&s_best[r], p);
                }
            }
        }
    }
    __syncthreads();

    // ---- stage D: gather + loss partial (4 rows per warp) ----
    {
        #pragma unroll
        for (int k = 0; k < 4; k++) {
            int r = wid * 4 + k;
            int rowg = qbase + r;
            int e = (int)(s_best[r] & 0xFFFFFFFFull) & (NE - 1);
            const float4* evw = (const float4*)&g_enorm[(size_t)e * DIM];
            const float4* zvw = (const float4*)&g_znorm[(size_t)rowg * DIM];
            float4 a0 = evw[tx], a1 = evw[tx + 32];
            float4 b0 = zvw[tx], b1 = zvw[tx + 32];
            if (write_zq) {
                float4* o = (float4*)&zq_out[(size_t)rowg * DIM];
                o[tx]      = a0;
                o[tx + 32] = a1;
            }
            float dx, s = 0.f;
            dx = a0.x - b0.x; s += dx * dx;  dx = a0.y - b0.y; s += dx * dx;
            dx = a0.z - b0.z; s += dx * dx;  dx = a0.w - b0.w; s += dx * dx;
            dx = a1.x - b1.x; s += dx * dx;  dx = a1.y - b1.y; s += dx * dx;
            dx = a1.z - b1.z; s += dx * dx;  dx = a1.w - b1.w; s += dx * dx;
            #pragma unroll
            for (int off = 16; off; off >>= 1) s += __shfl_xor_sync(0xffffffffu, s, off);
            if (tx == 0) {
                g_partial[rowg] = s;
                if (idxf_out) idxf_out[rowg] = (float)e;
            }
        }
    }
    gridbar(gen0 + 2);

    // ================= Phase 3: loss finalize (block 0) ========================
    if (blockIdx.x == 0) {
        float* red = (float*)smem;
        float s = 0.f;
        for (int i = tid; i < NQ; i += NTHR) s += g_partial[i];
        red[tid] = s;
        __syncthreads();
        for (int off = NTHR / 2; off; off >>= 1) {
            if (tid < off) red[tid] += red[tid + off];
            __syncthreads();
        }
        if (tid == 0 && loss_out) loss_out[0] = 1.25f * red[0] / (float)ZQ_ELEMS;
    }
}

// ---------------- launch (no __device__ symbols below!) ----------------
extern "C" void kernel_launch(void* const* d_in, const int* in_sizes, int n_in,
                              void* d_out, int out_size) {
    const float* z  = (const float*)d_in[0];
    const float* ew = (const float*)d_in[1];
    float* out = (float*)d_out;

    int   write_zq = 0;
    float* lossp = nullptr;
    float* idxf  = nullptr;
    if (out_size >= ZQ_ELEMS) {
        write_zq = 1;
        long R = (long)out_size - (long)ZQ_ELEMS;
        if (R >= (long)NQ + 1)      { lossp = out + ZQ_ELEMS; idxf = out + ZQ_ELEMS + 1; }
        else if (R == (long)NQ)     { idxf = out + ZQ_ELEMS; }
        else if (R >= 1)            { lossp = out + ZQ_ELEMS; }
    } else if (out_size == NQ) {
        idxf = out;
    } else if (out_size == 1) {
        lossp = out;
    }

    static int smem_set = 0;
    if (!smem_set) {
        cudaFuncSetAttribute(vq_fused, cudaFuncAttributeMaxDynamicSharedMemorySize, SMEM_SC);
        smem_set = 1;
    }

    vq_fused<<<NBLK, NTHR, SMEM_SC>>>(z, ew, out, idxf, lossp, write_zq);
}

// round 16
// speedup vs baseline: 1.2514x; 1.2514x over previous
#include <cuda_runtime.h>
#include <cuda_fp16.h>
#include <cstdint>

#define DIM 256
#define NQ  8192
#define NE  8192
#define NW  64               // 64 int32 words per row (256 int8)
#define ZQ_ELEMS (NQ * DIM)
#define NTILE 32             // code tiles of 256
#define NBLK  128
#define NTHR  1024
#define LIST_CAP 4096

// smem: As 16K | Bs 2x64K | gmin16 fp16 64x512 = 64K  -> 212992 B
#define AS_OFF   0
#define BS_OFF   16384
#define GM_OFF   (16384 + 131072)
#define SMEM_SC  (16384 + 131072 + 65536)

// ---------------- device scratch (device-side references only) ----------------
__device__ float g_znorm[NQ * DIM];
__device__ float g_znorm2[NQ];
__device__ float g_zinv[NQ];
__device__ float g_zdel[NQ];
__device__ int   g_qz[NQ * NW];
__device__ float g_enorm[NE * DIM];
__device__ float g_enorm2[NE];
__device__ float g_einv[NE];
__device__ int   g_qeT[NW * NE];     // word-major: [word][code]
__device__ unsigned g_demaxU;
__device__ float g_partial[NQ];
__device__ unsigned g_count;
__device__ unsigned g_gen;

// ---------------- async-copy helpers (sm_80-era PTX) ----------------
__device__ __forceinline__ uint32_t smem_u32(const void* p) {
    uint32_t a;
    asm("{ .reg .u64 t; cvta.to.shared.u64 t, %1; cvt.u32.u64 %0, t; }" : "=r"(a) : "l"(p));
    return a;
}
__device__ __forceinline__ void cp16(uint32_t dst, const void* src) {
    asm volatile("cp.async.cg.shared.global [%0], [%1], 16;" :: "r"(dst), "l"(src));
}
__device__ __forceinline__ void cp_commit() { asm volatile("cp.async.commit_group;"); }
template <int N>
__device__ __forceinline__ void cp_wait() { asm volatile("cp.async.wait_group %0;" :: "n"(N)); }

// ---------------- grid barrier (128 blocks co-resident: 1 block/SM) ----------
__device__ __forceinline__ void gridbar(unsigned expect) {
    __threadfence();
    __syncthreads();
    if (threadIdx.x == 0) {
        unsigned t = atomicAdd(&g_count, 1);
        if (t == NBLK - 1) {
            g_count = 0;
            __threadfence();
            atomicAdd(&g_gen, 1);
        } else {
            while (atomicAdd(&g_gen, 0) < expect) { }
            __threadfence();
        }
    }
    __syncthreads();
}

// ---------------- the whole pipeline in ONE kernel ----------------
__global__ __launch_bounds__(NTHR, 1)
void vq_fused(const float* __restrict__ z_in, const float* __restrict__ e_in,
              float* __restrict__ zq_out, float* __restrict__ idxf_out,
              float* __restrict__ loss_out, int write_zq) {
    extern __shared__ char smem[];
    int*    As     = (int*)(smem + AS_OFF);     // [64 words][64 rows]
    int*    Bs     = (int*)(smem + BS_OFF);     // [2][64 words][256 codes]
    __half* gmin16 = (__half*)(smem + GM_OFF);  // [64 rows][512 groups-of-16]
    __shared__ float s_thr[64];
    __shared__ unsigned long long s_best[64];
    __shared__ int s_cnt;
    __shared__ unsigned s_gen0;

    const int tid = threadIdx.x;
    const int tx  = tid & 31;
    const int wid = tid >> 5;

    if (tid == 0) s_gen0 = g_gen;
    __syncthreads();
    const unsigned gen0 = s_gen0;

    // ================= Phase 1: L2-normalize + int8 quantize (16384 rows) ======
    {
        int warpG = blockIdx.x * 32 + wid;            // 0..4095
        #pragma unroll 1
        for (int it = 0; it < 4; it++) {
            int r16 = warpG + it * 4096;              // 0..16383
            int is_code = (r16 < NE);
            int row = is_code ? r16 : (r16 - NE);
            const float* in = is_code ? e_in : z_in;
            float* outv = is_code ? g_enorm : g_znorm;

            const float4* src = (const float4*)(in + (size_t)row * DIM);
            float4 v0 = src[tx];
            float4 v1 = src[tx + 32];
            float s = v0.x*v0.x + v0.y*v0.y + v0.z*v0.z + v0.w*v0.w
                    + v1.x*v1.x + v1.y*v1.y + v1.z*v1.z + v1.w*v1.w;
            #pragma unroll
            for (int off = 16; off; off >>= 1) s += __shfl_xor_sync(0xffffffffu, s, off);
            float inv = 1.0f / fmaxf(sqrtf(s), 1e-12f);
            v0.x *= inv; v0.y *= inv; v0.z *= inv; v0.w *= inv;
            v1.x *= inv; v1.y *= inv; v1.z *= inv; v1.w *= inv;
            float4* dst = (float4*)(outv + (size_t)row * DIM);
            dst[tx]      = v0;
            dst[tx + 32] = v1;

            float vals[8] = {v0.x, v0.y, v0.z, v0.w, v1.x, v1.y, v1.z, v1.w};
            float s2 = 0.f;
            #pragma unroll
            for (int j = 0; j < 8; j++) s2 += vals[j] * vals[j];
            #pragma unroll
            for (int off = 16; off; off >>= 1) s2 += __shfl_xor_sync(0xffffffffu, s2, off);

            float mx = 0.f;
            #pragma unroll
            for (int j = 0; j < 8; j++) mx = fmaxf(mx, fabsf(vals[j]));
            #pragma unroll
            for (int off = 16; off; off >>= 1) mx = fmaxf(mx, __shfl_xor_sync(0xffffffffu, mx, off));
            float sc    = 127.0f / mx;
            float scinv = mx / 127.0f;

            int h[8];
            float dsum = 0.f;
            #pragma unroll
            for (int j = 0; j < 8; j++) {
                h[j] = (int)rintf(vals[j] * sc);
                float e = vals[j] - (float)h[j] * scinv;
                dsum += e * e;
            }
            #pragma unroll
            for (int off = 16; off; off >>= 1) dsum += __shfl_xor_sync(0xffffffffu, dsum, off);

            int w0 = (h[0] & 0xFF) | ((h[1] & 0xFF) << 8) | ((h[2] & 0xFF) << 16) | (h[3] << 24);
            int w1 = (h[4] & 0xFF) | ((h[5] & 0xFF) << 8) | ((h[6] & 0xFF) << 16) | (h[7] << 24);
            if (is_code) {
                // word-major for transpose-free cp.async in phase 2
                g_qeT[(size_t)tx * NE + row]        = w0;
                g_qeT[(size_t)(tx + 32) * NE + row] = w1;
            } else {
                g_qz[(size_t)row * NW + tx]      = w0;
                g_qz[(size_t)row * NW + 32 + tx] = w1;
            }
            if (tx == 0) {
                float del = sqrtf(dsum);
                if (is_code) {
                    g_enorm2[row] = s2; g_einv[row] = scinv;
                    atomicMax(&g_demaxU, __float_as_uint(del));
                } else {
                    g_znorm2[row] = s2; g_zinv[row] = scinv; g_zdel[row] = del;
                }
            }
        }
    }
    gridbar(gen0 + 1);

    // ================= Phase 2: dp4a screen (8 rows x 2 codes per thread) ======
    const int wm  = wid >> 2;         // 0..7 -> rows wm*8..+7
    const int cgr = wid & 3;          // codes cgr*64 + tx*2, +1
    const int qbase = blockIdx.x * 64;

    // A load, transposed into smem [word][row]
    {
        int row = tid >> 4, p = tid & 15;    // 64 rows x 16 threads
        int w = p * 4;
        int4 v = *(const int4*)&g_qz[(size_t)(qbase + row) * NW + w];
        As[(w + 0) * 64 + row] = v.x;
        As[(w + 1) * 64 + row] = v.y;
        As[(w + 2) * 64 + row] = v.z;
        As[(w + 3) * 64 + row] = v.w;
    }

    const uint32_t bs_base = smem_u32(Bs);

    // issue tile 0 (4096 16B units / 1024 thr = 4 each); word-major src: coalesced
    {
        #pragma unroll
        for (int j = 0; j < 4; j++) {
            int u  = tid + j * 1024;         // 0..4095
            int w  = u >> 6;
            int c4 = u & 63;
            cp16(bs_base + (uint32_t)u * 16,
                 &g_qeT[(size_t)w * NE + 0 * 256 + c4 * 4]);
        }
        cp_commit();
    }

    int acc[8][2];

    #pragma unroll 1
    for (int t = 0; t < NTILE; t++) {
        if (t + 1 < NTILE) {
            uint32_t bdst = bs_base + (uint32_t)(((t + 1) & 1) * 65536);
            #pragma unroll
            for (int j = 0; j < 4; j++) {
                int u  = tid + j * 1024;
                int w  = u >> 6;
                int c4 = u & 63;
                cp16(bdst + (uint32_t)u * 16,
                     &g_qeT[(size_t)w * NE + (t + 1) * 256 + c4 * 4]);
            }
            cp_commit();
            cp_wait<1>();
        } else {
            cp_wait<0>();
        }
        __syncthreads();

        #pragma unroll
        for (int i = 0; i < 8; i++) { acc[i][0] = 0; acc[i][1] = 0; }

        const int* B = Bs + (t & 1) * 16384 + cgr * 64;
        #pragma unroll 8
        for (int kw = 0; kw < 64; kw++) {
            int4 a0 = *(const int4*)&As[kw * 64 + wm * 8];
            int4 a1 = *(const int4*)&As[kw * 64 + wm * 8 + 4];
            int2 b  = *(const int2*)&B[kw * 256 + tx * 2];
            acc[0][0] = __dp4a(a0.x, b.x, acc[0][0]); acc[0][1] = __dp4a(a0.x, b.y, acc[0][1]);
            acc[1][0] = __dp4a(a0.y, b.x, acc[1][0]); acc[1][1] = __dp4a(a0.y, b.y, acc[1][1]);
            acc[2][0] = __dp4a(a0.z, b.x, acc[2][0]); acc[2][1] = __dp4a(a0.z, b.y, acc[2][1]);
            acc[3][0] = __dp4a(a0.w, b.x, acc[3][0]); acc[3][1] = __dp4a(a0.w, b.y, acc[3][1]);
            acc[4][0] = __dp4a(a1.x, b.x, acc[4][0]); acc[4][1] = __dp4a(a1.x, b.y, acc[4][1]);
            acc[5][0] = __dp4a(a1.y, b.x, acc[5][0]); acc[5][1] = __dp4a(a1.y, b.y, acc[5][1]);
            acc[6][0] = __dp4a(a1.z, b.x, acc[6][0]); acc[6][1] = __dp4a(a1.z, b.y, acc[6][1]);
            acc[7][0] = __dp4a(a1.w, b.x, acc[7][0]); acc[7][1] = __dp4a(a1.w, b.y, acc[7][1]);
        }

        // epilogue: per-row per-16-code fp16 min
        {
            int colb = t * 256 + cgr * 64 + tx * 2;
            float2 e2  = *(const float2*)&g_enorm2[colb];
            float2 civ = *(const float2*)&g_einv[colb];
            float4 z2a = *(const float4*)&g_znorm2[qbase + wm * 8];
            float4 z2b = *(const float4*)&g_znorm2[qbase + wm * 8 + 4];
            float4 qia = *(const float4*)&g_zinv[qbase + wm * 8];
            float4 qib = *(const float4*)&g_zinv[qbase + wm * 8 + 4];
            float z2arr[8] = {z2a.x, z2a.y, z2a.z, z2a.w, z2b.x, z2b.y, z2b.z, z2b.w};
            float qiarr[8] = {qia.x, qia.y, qia.z, qia.w, qib.x, qib.y, qib.z, qib.w};
            int g16 = t * 16 + cgr * 4 + (tx >> 3);
            #pragma unroll
            for (int i = 0; i < 8; i++) {
                float sc = qiarr[i];
                float k0 = z2arr[i] + e2.x - 2.0f * ((float)acc[i][0] * (sc * civ.x));
                float k1 = z2arr[i] + e2.y - 2.0f * ((float)acc[i][1] * (sc * civ.y));
                float m = fminf(k0, k1);
                m = fminf(m, __shfl_xor_sync(0xffffffffu, m, 1));
                m = fminf(m, __shfl_xor_sync(0xffffffffu, m, 2));
                m = fminf(m, __shfl_xor_sync(0xffffffffu, m, 4));
                if ((tx & 7) == 0)
                    gmin16[(wm * 8 + i) * 512 + g16] = __float2half_rn(m);
            }
        }
        // CRITICAL: all warps must finish reading Bs[t&1] (and writing gmin16)
        // before any warp issues next iteration's cp.async into that buffer.
        __syncthreads();
    }

    // init tail shared state
    if (tid == 0) s_cnt = 0;
    if (tid < 64) s_best[tid] = 0xFFFFFFFFFFFFFFFFull;
    __syncthreads();

    // ---- stage A: per-row lm + threshold (2 rows per warp) ----
    {
        float D = __uint_as_float(g_demaxU);
        #pragma unroll
        for (int k = 0; k < 2; k++) {
            int r = wid * 2 + k;
            float lm = 3.4e38f;
            const __half* gr = &gmin16[r * 512];
            #pragma unroll
            for (int p = 0; p < 2; p++) {
                uint4 v = *(const uint4*)&gr[p * 256 + tx * 8];
                uint32_t ws[4] = {v.x, v.y, v.z, v.w};
                #pragma unroll
                for (int u = 0; u < 4; u++) {
                    float2 f = __half22float2(*(__half2*)&ws[u]);
                    lm = fminf(lm, fminf(f.x, f.y));
                }
            }
            #pragma unroll
            for (int off = 16; off; off >>= 1) lm = fminf(lm, __shfl_xor_sync(0xffffffffu, lm, off));
            if (tx == 0) {
                float dq = g_zdel[qbase + r];
                float M = 2.0f * (dq + D + dq * D);
                s_thr[r] = lm + 2.0f * M + 4e-3f;    // sound window + fp16 slack
            }
        }
    }
    __syncthreads();

    // ---- stage B: scan + push candidate (row, group16) into list ----
    int* list = As;   // reuse As region: 4096 ints
    {
        #pragma unroll 1
        for (int i = 0; i < 4; i++) {
            int u4 = tid + i * 1024;                 // uint4 over 64x512 halves
            int r = u4 >> 6;
            float thr = s_thr[r];
            uint4 v = *(const uint4*)&gmin16[u4 * 8];
            int gbase = (u4 & 63) * 8;
            uint32_t ws[4] = {v.x, v.y, v.z, v.w};
            #pragma unroll
            for (int u = 0; u < 4; u++) {
                float2 f = __half22float2(*(__half2*)&ws[u]);
                if (f.x <= thr) { int p = atomicAdd(&s_cnt, 1); if (p < LIST_CAP) list[p] = (r << 16) | (gbase + u * 2); }
                if (f.y <= thr) { int p = atomicAdd(&s_cnt, 1); if (p < LIST_CAP) list[p] = (r << 16) | (gbase + u * 2 + 1); }
            }
        }
    }
    __syncthreads();
    int ncand = s_cnt;

    // ---- stage C: exact rescore (warp per entry; 16 codes per entry) ----
    if (ncand <= LIST_CAP) {
        #pragma unroll 1
        for (int e = wid; e < ncand; e += 32) {
            int ent = list[e];
            int r   = ent >> 16;
            int g16 = ent & 0xFFFF;
            int rowg = qbase + r;
            float z2r = g_znorm2[rowg];
            const float4* zvw = (const float4*)&g_znorm[(size_t)rowg * DIM];
            float4 za = zvw[tx], zb = zvw[tx + 32];
            #pragma unroll 1
            for (int kk = 0; kk < 16; kk++) {
                int code = g16 * 16 + kk;
                const float4* ev = (const float4*)&g_enorm[(size_t)code * DIM];
                float4 ea = ev[tx], eb = ev[tx + 32];
                float d = za.x*ea.x + za.y*ea.y + za.z*ea.z + za.w*ea.w
                        + zb.x*eb.x + zb.y*eb.y + zb.z*eb.z + zb.w*eb.w;
                #pragma unroll
                for (int off = 16; off; off >>= 1) d += __shfl_xor_sync(0xffffffffu, d, off);
                if (tx == 0) {
                    float key = z2r + g_enorm2[code] - 2.0f * d;
                    unsigned long long p =
                        ((unsigned long long)__float_as_uint(key) << 32) | (unsigned)code;
                    atomicMin(&s_best[r], p);
                }
            }
        }
    } else {
        // sound fallback (practically never)
        #pragma unroll 1
        for (int e = wid; e < 64 * 512; e += 32) {
            int r   = e >> 9;
            int g16 = e & 511;
            if (__half2float(gmin16[r * 512 + g16]) > s_thr[r]) continue;
            int rowg = qbase + r;
            float z2r = g_znorm2[rowg];
            const float4* zvw = (const float4*)&g_znorm[(size_t)rowg * DIM];
            float4 za = zvw[tx], zb = zvw[tx + 32];
            for (int kk = 0; kk < 16; kk++) {
                int code = g16 * 16 + kk;
                const float4* ev = (const float4*)&g_enorm[(size_t)code * DIM];
                float4 ea = ev[tx], eb = ev[tx + 32];
                float d = za.x*ea.x + za.y*ea.y + za.z*ea.z + za.w*ea.w
                        + zb.x*eb.x + zb.y*eb.y + zb.z*eb.z + zb.w*eb.w;
                #pragma unroll
                for (int off = 16; off; off >>= 1) d += __shfl_xor_sync(0xffffffffu, d, off);
                if (tx == 0) {
                    float key = z2r + g_enorm2[code] - 2.0f * d;
                    unsigned long long p =
                        ((unsigned long long)__float_as_uint(key) << 32) | (unsigned)code;
                    atomicMin(&s_best[r], p);
                }
            }
        }
    }
    __syncthreads();

    // ---- stage D: gather + loss partial (2 rows per warp) ----
    {
        #pragma unroll
        for (int k = 0; k < 2; k++) {
            int r = wid * 2 + k;
            int rowg = qbase + r;
            int e = (int)(s_best[r] & 0xFFFFFFFFull) & (NE - 1);
            const float4* evw = (const float4*)&g_enorm[(size_t)e * DIM];
            const float4* zvw = (const float4*)&g_znorm[(size_t)rowg * DIM];
            float4 a0 = evw[tx], a1 = evw[tx + 32];
            float4 b0 = zvw[tx], b1 = zvw[tx + 32];
            if (write_zq) {
                float4* o = (float4*)&zq_out[(size_t)rowg * DIM];
                o[tx]      = a0;
                o[tx + 32] = a1;
            }
            float dx, s = 0.f;
            dx = a0.x - b0.x; s += dx * dx;  dx = a0.y - b0.y; s += dx * dx;
            dx = a0.z - b0.z; s += dx * dx;  dx = a0.w - b0.w; s += dx * dx;
            dx = a1.x - b1.x; s += dx * dx;  dx = a1.y - b1.y; s += dx * dx;
            dx = a1.z - b1.z; s += dx * dx;  dx = a1.w - b1.w; s += dx * dx;
            #pragma unroll
            for (int off = 16; off; off >>= 1) s += __shfl_xor_sync(0xffffffffu, s, off);
            if (tx == 0) {
                g_partial[rowg] = s;
                if (idxf_out) idxf_out[rowg] = (float)e;
            }
        }
    }
    gridbar(gen0 + 2);

    // ================= Phase 3: loss finalize (block 0) ========================
    if (blockIdx.x == 0) {
        float* red = (float*)smem;
        float s = 0.f;
        for (int i = tid; i < NQ; i += NTHR) s += g_partial[i];
        red[tid] = s;
        __syncthreads();
        for (int off = NTHR / 2; off; off >>= 1) {
            if (tid < off) red[tid] += red[tid + off];
            __syncthreads();
        }
        if (tid == 0 && loss_out) loss_out[0] = 1.25f * red[0] / (float)ZQ_ELEMS;
    }
}

// ---------------- launch (no __device__ symbols below!) ----------------
extern "C" void kernel_launch(void* const* d_in, const int* in_sizes, int n_in,
                              void* d_out, int out_size) {
    const float* z  = (const float*)d_in[0];
    const float* ew = (const float*)d_in[1];
    float* out = (float*)d_out;

    int   write_zq = 0;
    float* lossp = nullptr;
    float* idxf  = nullptr;
    if (out_size >= ZQ_ELEMS) {
        write_zq = 1;
        long R = (long)out_size - (long)ZQ_ELEMS;
        if (R >= (long)NQ + 1)      { lossp = out + ZQ_ELEMS; idxf = out + ZQ_ELEMS + 1; }
        else if (R == (long)NQ)     { idxf = out + ZQ_ELEMS; }
        else if (R >= 1)            { lossp = out + ZQ_ELEMS; }
    } else if (out_size == NQ) {
        idxf = out;
    } else if (out_size == 1) {
        lossp = out;
    }

    static int smem_set = 0;
    if (!smem_set) {
        cudaFuncSetAttribute(vq_fused, cudaFuncAttributeMaxDynamicSharedMemorySize, SMEM_SC);
        smem_set = 1;
    }

    vq_fused<<<NBLK, NTHR, SMEM_SC>>>(z, ew, out, idxf, lossp, write_zq);
}

// round 17
// speedup vs baseline: 1.4407x; 1.1513x over previous
#include <cuda_runtime.h>
#include <cuda_fp16.h>
#include <cstdint>

#define DIM 256
#define NQ  8192
#define NE  8192
#define NW  64               // 64 int32 words per row (256 int8)
#define ZQ_ELEMS (NQ * DIM)
#define NTILE 32             // code tiles of 256
#define NBLK  128
#define NTHR  1024
#define LIST_CAP 4096

// smem: As 16K | Bs 64K (single) | gmin8 fp16 64x1024 = 128K  -> 212992 B
#define AS_OFF   0
#define BS_OFF   16384
#define GM_OFF   (16384 + 65536)
#define SMEM_SC  (16384 + 65536 + 131072)

// ---------------- device scratch (device-side references only) ----------------
__device__ float g_znorm[NQ * DIM];
__device__ float g_znorm2[NQ];
__device__ float g_zinv[NQ];
__device__ float g_zdel[NQ];
__device__ int   g_qz[NQ * NW];
__device__ float g_enorm[NE * DIM];
__device__ float g_enorm2[NE];
__device__ float g_einv[NE];
__device__ int   g_qe[NE * NW];
__device__ unsigned g_demaxU;
__device__ float g_partial[NQ];
__device__ unsigned g_count;
__device__ unsigned g_gen;

// ---------------- grid barrier (128 blocks co-resident: 1 block/SM) ----------
__device__ __forceinline__ void gridbar(unsigned expect) {
    __threadfence();
    __syncthreads();
    if (threadIdx.x == 0) {
        unsigned t = atomicAdd(&g_count, 1);
        if (t == NBLK - 1) {
            g_count = 0;
            __threadfence();
            atomicAdd(&g_gen, 1);
        } else {
            while (atomicAdd(&g_gen, 0) < expect) { }
            __threadfence();
        }
    }
    __syncthreads();
}

// ---------------- the whole pipeline in ONE kernel ----------------
__global__ __launch_bounds__(NTHR, 1)
void vq_fused(const float* __restrict__ z_in, const float* __restrict__ e_in,
              float* __restrict__ zq_out, float* __restrict__ idxf_out,
              float* __restrict__ loss_out, int write_zq) {
    extern __shared__ char smem[];
    int*    As    = (int*)(smem + AS_OFF);     // [64 words][64 rows]
    int*    Bs    = (int*)(smem + BS_OFF);     // [64 words][256 codes], XOR-swizzled
    __half* gmin8 = (__half*)(smem + GM_OFF);  // [64 rows][1024 groups-of-8]
    __shared__ float s_thr[64];
    __shared__ unsigned long long s_best[64];
    __shared__ int s_cnt;
    __shared__ unsigned s_gen0;

    const int tid = threadIdx.x;
    const int tx  = tid & 31;
    const int wid = tid >> 5;

    if (tid == 0) s_gen0 = g_gen;
    __syncthreads();
    const unsigned gen0 = s_gen0;

    // ================= Phase 1: L2-normalize + int8 quantize (16384 rows) ======
    {
        int warpG = blockIdx.x * 32 + wid;            // 0..4095
        #pragma unroll 1
        for (int it = 0; it < 4; it++) {
            int r16 = warpG + it * 4096;              // 0..16383
            int is_code = (r16 < NE);
            int row = is_code ? r16 : (r16 - NE);
            const float* in = is_code ? e_in : z_in;
            float* outv = is_code ? g_enorm : g_znorm;

            const float4* src = (const float4*)(in + (size_t)row * DIM);
            float4 v0 = src[tx];
            float4 v1 = src[tx + 32];
            float s = v0.x*v0.x + v0.y*v0.y + v0.z*v0.z + v0.w*v0.w
                    + v1.x*v1.x + v1.y*v1.y + v1.z*v1.z + v1.w*v1.w;
            #pragma unroll
            for (int off = 16; off; off >>= 1) s += __shfl_xor_sync(0xffffffffu, s, off);
            float inv = 1.0f / fmaxf(sqrtf(s), 1e-12f);
            v0.x *= inv; v0.y *= inv; v0.z *= inv; v0.w *= inv;
            v1.x *= inv; v1.y *= inv; v1.z *= inv; v1.w *= inv;
            float4* dst = (float4*)(outv + (size_t)row * DIM);
            dst[tx]      = v0;
            dst[tx + 32] = v1;

            float vals[8] = {v0.x, v0.y, v0.z, v0.w, v1.x, v1.y, v1.z, v1.w};
            float s2 = 0.f;
            #pragma unroll
            for (int j = 0; j < 8; j++) s2 += vals[j] * vals[j];
            #pragma unroll
            for (int off = 16; off; off >>= 1) s2 += __shfl_xor_sync(0xffffffffu, s2, off);

            float mx = 0.f;
            #pragma unroll
            for (int j = 0; j < 8; j++) mx = fmaxf(mx, fabsf(vals[j]));
            #pragma unroll
            for (int off = 16; off; off >>= 1) mx = fmaxf(mx, __shfl_xor_sync(0xffffffffu, mx, off));
            float sc    = 127.0f / mx;
            float scinv = mx / 127.0f;

            int h[8];
            float dsum = 0.f;
            #pragma unroll
            for (int j = 0; j < 8; j++) {
                h[j] = (int)rintf(vals[j] * sc);
                float e = vals[j] - (float)h[j] * scinv;
                dsum += e * e;
            }
            #pragma unroll
            for (int off = 16; off; off >>= 1) dsum += __shfl_xor_sync(0xffffffffu, dsum, off);

            int w0 = (h[0] & 0xFF) | ((h[1] & 0xFF) << 8) | ((h[2] & 0xFF) << 16) | (h[3] << 24);
            int w1 = (h[4] & 0xFF) | ((h[5] & 0xFF) << 8) | ((h[6] & 0xFF) << 16) | (h[7] << 24);
            int* qp = is_code ? g_qe : g_qz;
            qp[(size_t)row * NW + tx]      = w0;
            qp[(size_t)row * NW + 32 + tx] = w1;
            if (tx == 0) {
                float del = sqrtf(dsum);
                if (is_code) {
                    g_enorm2[row] = s2; g_einv[row] = scinv;
                    atomicMax(&g_demaxU, __float_as_uint(del));
                } else {
                    g_znorm2[row] = s2; g_zinv[row] = scinv; g_zdel[row] = del;
                }
            }
        }
    }
    gridbar(gen0 + 1);

    // ================= Phase 2: dp4a screen (4 rows x 4 codes per thread) ======
    const int wm = wid >> 1;          // 0..15 -> rows wm*4..+3
    const int wn = wid & 1;           // col half
    const int qbase = blockIdx.x * 64;

    // A load, transposed: [word][row]
    {
        int row = tid >> 4, p = tid & 15;    // 64 rows x 16 threads
        int w = p * 4;
        int4 v = *(const int4*)&g_qz[(size_t)(qbase + row) * NW + w];
        As[(w + 0) * 64 + row] = v.x;
        As[(w + 1) * 64 + row] = v.y;
        As[(w + 2) * 64 + row] = v.z;
        As[(w + 3) * 64 + row] = v.w;
    }

    // per-row epilogue scalars
    float z2s[4], qiv[4];
    #pragma unroll
    for (int i = 0; i < 4; i++) {
        int r = qbase + wm * 4 + i;
        z2s[i] = g_znorm2[r];
        qiv[i] = g_zinv[r];
    }

    // B staging: thread -> code c = tid>>2, quarter q = tid&3 (words q*16..+15)
    // Swizzled smem position of (word w, code c): w*256 + (c ^ ((w>>4)<<3)).
    // For this thread all stored words have w>>4 == q, so csw is constant.
    const int c   = tid >> 2;
    const int q   = tid & 3;
    const int csw = c ^ (q << 3);
    int4 br[4];
    #pragma unroll
    for (int j = 0; j < 4; j++)
        br[j] = *(const int4*)&g_qe[(size_t)c * NW + q * 16 + j * 4];

    int acc[4][4];

    #pragma unroll 1
    for (int t = 0; t < NTILE; t++) {
        __syncthreads();    // prior tile's Bs reads complete
        #pragma unroll
        for (int j = 0; j < 4; j++) {
            int w = q * 16 + j * 4;
            Bs[(w + 0) * 256 + csw] = br[j].x;
            Bs[(w + 1) * 256 + csw] = br[j].y;
            Bs[(w + 2) * 256 + csw] = br[j].z;
            Bs[(w + 3) * 256 + csw] = br[j].w;
        }
        __syncthreads();
        if (t + 1 < NTILE) {
            #pragma unroll
            for (int j = 0; j < 4; j++)
                br[j] = *(const int4*)&g_qe[(size_t)((t + 1) * 256 + c) * NW + q * 16 + j * 4];
        }

        #pragma unroll
        for (int i = 0; i < 4; i++) {
            acc[i][0] = 0; acc[i][1] = 0; acc[i][2] = 0; acc[i][3] = 0;
        }
        const int cbase = wn * 128 + tx * 4;   // true code base for this thread
        #pragma unroll 8
        for (int kw = 0; kw < 64; kw++) {
            int4 a = *(const int4*)&As[kw * 64 + wm * 4];
            int4 b = *(const int4*)&Bs[kw * 256 + (cbase ^ ((kw >> 4) << 3))];
            acc[0][0] = __dp4a(a.x, b.x, acc[0][0]); acc[0][1] = __dp4a(a.x, b.y, acc[0][1]);
            acc[0][2] = __dp4a(a.x, b.z, acc[0][2]); acc[0][3] = __dp4a(a.x, b.w, acc[0][3]);
            acc[1][0] = __dp4a(a.y, b.x, acc[1][0]); acc[1][1] = __dp4a(a.y, b.y, acc[1][1]);
            acc[1][2] = __dp4a(a.y, b.z, acc[1][2]); acc[1][3] = __dp4a(a.y, b.w, acc[1][3]);
            acc[2][0] = __dp4a(a.z, b.x, acc[2][0]); acc[2][1] = __dp4a(a.z, b.y, acc[2][1]);
            acc[2][2] = __dp4a(a.z, b.z, acc[2][2]); acc[2][3] = __dp4a(a.z, b.w, acc[2][3]);
            acc[3][0] = __dp4a(a.w, b.x, acc[3][0]); acc[3][1] = __dp4a(a.w, b.y, acc[3][1]);
            acc[3][2] = __dp4a(a.w, b.z, acc[3][2]); acc[3][3] = __dp4a(a.w, b.w, acc[3][3]);
        }

        // epilogue: per-row per-8-code fp16 min
        {
            int colb = t * 256 + wn * 128 + tx * 4;
            float4 e2  = *(const float4*)&g_enorm2[colb];
            float4 civ = *(const float4*)&g_einv[colb];
            int g8 = t * 32 + wn * 16 + (tx >> 1);
            #pragma unroll
            for (int i = 0; i < 4; i++) {
                float sc = qiv[i];
                float k0 = z2s[i] + e2.x - 2.0f * ((float)acc[i][0] * (sc * civ.x));
                float k1 = z2s[i] + e2.y - 2.0f * ((float)acc[i][1] * (sc * civ.y));
                float k2 = z2s[i] + e2.z - 2.0f * ((float)acc[i][2] * (sc * civ.z));
                float k3 = z2s[i] + e2.w - 2.0f * ((float)acc[i][3] * (sc * civ.w));
                float m = fminf(fminf(k0, k1), fminf(k2, k3));
                m = fminf(m, __shfl_xor_sync(0xffffffffu, m, 1));
                if ((tx & 1) == 0)
                    gmin8[(wm * 4 + i) * 1024 + g8] = __float2half_rn(m);
            }
        }
    }

    // init tail shared state
    if (tid == 0) s_cnt = 0;
    if (tid < 64) s_best[tid] = 0xFFFFFFFFFFFFFFFFull;
    __syncthreads();

    // ---- stage A: per-row lm + threshold (2 rows per warp) ----
    {
        float D = __uint_as_float(g_demaxU);
        #pragma unroll
        for (int k = 0; k < 2; k++) {
            int r = wid * 2 + k;
            float lm = 3.4e38f;
            const __half* gr = &gmin8[r * 1024];
            #pragma unroll
            for (int p = 0; p < 4; p++) {
                uint4 v = *(const uint4*)&gr[p * 256 + tx * 8];
                uint32_t ws[4] = {v.x, v.y, v.z, v.w};
                #pragma unroll
                for (int u = 0; u < 4; u++) {
                    float2 f = __half22float2(*(__half2*)&ws[u]);
                    lm = fminf(lm, fminf(f.x, f.y));
                }
            }
            #pragma unroll
            for (int off = 16; off; off >>= 1) lm = fminf(lm, __shfl_xor_sync(0xffffffffu, lm, off));
            if (tx == 0) {
                float dq = g_zdel[qbase + r];
                float M = 2.0f * (dq + D + dq * D);
                s_thr[r] = lm + 2.0f * M + 4e-3f;    // sound window + fp16 slack
            }
        }
    }
    __syncthreads();

    // ---- stage B: scan + push candidate (row, group8) into list ----
    int* list = As;   // reuse As region: 4096 ints
    {
        #pragma unroll 1
        for (int i = 0; i < 8; i++) {
            int u8 = tid + i * 1024;                 // uint4 index, 8 halfs
            int r = u8 >> 7;
            float thr = s_thr[r];
            uint4 v = *(const uint4*)&gmin8[u8 * 8];
            int gbase = (u8 * 8) & 1023;
            uint32_t ws[4] = {v.x, v.y, v.z, v.w};
            #pragma unroll
            for (int u = 0; u < 4; u++) {
                float2 f = __half22float2(*(__half2*)&ws[u]);
                if (f.x <= thr) { int p = atomicAdd(&s_cnt, 1); if (p < LIST_CAP) list[p] = (r << 16) | (gbase + u * 2); }
                if (f.y <= thr) { int p = atomicAdd(&s_cnt, 1); if (p < LIST_CAP) list[p] = (r << 16) | (gbase + u * 2 + 1); }
            }
        }
    }
    __syncthreads();
    int ncand = s_cnt;

    // ---- stage C: exact rescore (warp per entry; 8 codes per entry) ----
    if (ncand <= LIST_CAP) {
        #pragma unroll 1
        for (int e = wid; e < ncand; e += 32) {
            int ent = list[e];
            int r  = ent >> 16;
            int g8 = ent & 0xFFFF;
            int rowg = qbase + r;
            float z2r = g_znorm2[rowg];
            const float4* zvw = (const float4*)&g_znorm[(size_t)rowg * DIM];
            float4 za = zvw[tx], zb = zvw[tx + 32];
            #pragma unroll 1
            for (int kk = 0; kk < 8; kk++) {
                int code = g8 * 8 + kk;
                const float4* ev = (const float4*)&g_enorm[(size_t)code * DIM];
                float4 ea = ev[tx], eb = ev[tx + 32];
                float d = za.x*ea.x + za.y*ea.y + za.z*ea.z + za.w*ea.w
                        + zb.x*eb.x + zb.y*eb.y + zb.z*eb.z + zb.w*eb.w;
                #pragma unroll
                for (int off = 16; off; off >>= 1) d += __shfl_xor_sync(0xffffffffu, d, off);
                if (tx == 0) {
                    float key = z2r + g_enorm2[code] - 2.0f * d;
                    unsigned long long p =
                        ((unsigned long long)__float_as_uint(key) << 32) | (unsigned)code;
                    atomicMin(&s_best[r], p);
                }
            }
        }
    } else {
        // sound fallback (practically never): re-test every group directly
        #pragma unroll 1
        for (int e = wid; e < 64 * 1024; e += 32) {
            int r  = e >> 10;
            int g8 = e & 1023;
            if (__half2float(gmin8[r * 1024 + g8]) > s_thr[r]) continue;
            int rowg = qbase + r;
            float z2r = g_znorm2[rowg];
            const float4* zvw = (const float4*)&g_znorm[(size_t)rowg * DIM];
            float4 za = zvw[tx], zb = zvw[tx + 32];
            for (int kk = 0; kk < 8; kk++) {
                int code = g8 * 8 + kk;
                const float4* ev = (const float4*)&g_enorm[(size_t)code * DIM];
                float4 ea = ev[tx], eb = ev[tx + 32];
                float d = za.x*ea.x + za.y*ea.y + za.z*ea.z + za.w*ea.w
                        + zb.x*eb.x + zb.y*eb.y + zb.z*eb.z + zb.w*eb.w;
                #pragma unroll
                for (int off = 16; off; off >>= 1) d += __shfl_xor_sync(0xffffffffu, d, off);
                if (tx == 0) {
                    float key = z2r + g_enorm2[code] - 2.0f * d;
                    unsigned long long p =
                        ((unsigned long long)__float_as_uint(key) << 32) | (unsigned)code;
                    atomicMin(&s_best[r], p);
                }
            }
        }
    }
    __syncthreads();

    // ---- stage D: gather + loss partial (2 rows per warp) ----
    {
        #pragma unroll
        for (int k = 0; k < 2; k++) {
            int r = wid * 2 + k;
            int rowg = qbase + r;
            int e = (int)(s_best[r] & 0xFFFFFFFFull) & (NE - 1);
            const float4* evw = (const float4*)&g_enorm[(size_t)e * DIM];
            const float4* zvw = (const float4*)&g_znorm[(size_t)rowg * DIM];
            float4 a0 = evw[tx], a1 = evw[tx + 32];
            float4 b0 = zvw[tx], b1 = zvw[tx + 32];
            if (write_zq) {
                float4* o = (float4*)&zq_out[(size_t)rowg * DIM];
                o[tx]      = a0;
                o[tx + 32] = a1;
            }
            float dx, s = 0.f;
            dx = a0.x - b0.x; s += dx * dx;  dx = a0.y - b0.y; s += dx * dx;
            dx = a0.z - b0.z; s += dx * dx;  dx = a0.w - b0.w; s += dx * dx;
            dx = a1.x - b1.x; s += dx * dx;  dx = a1.y - b1.y; s += dx * dx;
            dx = a1.z - b1.z; s += dx * dx;  dx = a1.w - b1.w; s += dx * dx;
            #pragma unroll
            for (int off = 16; off; off >>= 1) s += __shfl_xor_sync(0xffffffffu, s, off);
            if (tx == 0) {
                g_partial[rowg] = s;
                if (idxf_out) idxf_out[rowg] = (float)e;
            }
        }
    }
    gridbar(gen0 + 2);

    // ================= Phase 3: loss finalize (block 0) ========================
    if (blockIdx.x == 0) {
        float* red = (float*)smem;
        float s = 0.f;
        for (int i = tid; i < NQ; i += NTHR) s += g_partial[i];
        red[tid] = s;
        __syncthreads();
        for (int off = NTHR / 2; off; off >>= 1) {
            if (tid < off) red[tid] += red[tid + off];
            __syncthreads();
        }
        if (tid == 0 && loss_out) loss_out[0] = 1.25f * red[0] / (float)ZQ_ELEMS;
    }
}

// ---------------- launch (no __device__ symbols below!) ----------------
extern "C" void kernel_launch(void* const* d_in, const int* in_sizes, int n_in,
                              void* d_out, int out_size) {
    const float* z  = (const float*)d_in[0];
    const float* ew = (const float*)d_in[1];
    float* out = (float*)d_out;

    int   write_zq = 0;
    float* lossp = nullptr;
    float* idxf  = nullptr;
    if (out_size >= ZQ_ELEMS) {
        write_zq = 1;
        long R = (long)out_size - (long)ZQ_ELEMS;
        if (R >= (long)NQ + 1)      { lossp = out + ZQ_ELEMS; idxf = out + ZQ_ELEMS + 1; }
        else if (R == (long)NQ)     { idxf = out + ZQ_ELEMS; }
        else if (R >= 1)            { lossp = out + ZQ_ELEMS; }
    } else if (out_size == NQ) {
        idxf = out;
    } else if (out_size == 1) {
        lossp = out;
    }

    static int smem_set = 0;
    if (!smem_set) {
        cudaFuncSetAttribute(vq_fused, cudaFuncAttributeMaxDynamicSharedMemorySize, SMEM_SC);
        smem_set = 1;
    }

    vq_fused<<<NBLK, NTHR, SMEM_SC>>>(z, ew, out, idxf, lossp, write_zq);
}